// round 7
// baseline (speedup 1.0000x reference)
#include <cuda_runtime.h>
#include <cuda_fp16.h>
#include <math.h>
#include <stdint.h>

#define BB    8
#define CIN   64
#define COUT  64
#define NPTS  32768
#define R3    32768

// ---------------- scratch (static __device__ — no allocations) ----------------
__device__ float g_featT[(size_t)BB*NPTS*CIN];            // [b][n][c]
__device__ float g_acc  [(size_t)BB*R3*CIN];              // [b][x][y][z][c]
__device__ float g_cnt  [BB*R3];
__device__ __half g_v1h[(size_t)BB*R3*COUT];              // conv1 out fp16 [b][x][y][z][c]
__device__ float g_vox2[(size_t)BB*R3*COUT];              // conv2 out fp32 [b][x][y][z][c]
__device__ __half g_wh [2*27*64*64];                      // [which*27 + tap][co][ci]  fp16
__device__ float g_mean [BB*3];
__device__ float g_scale[BB];

// ---------------- helpers ----------------
__device__ __forceinline__ uint32_t smem_u32(const void* p){
    uint32_t a;
    asm("{ .reg .u64 t; cvta.to.shared.u64 t, %1; cvt.u32.u64 %0, t; }" : "=r"(a) : "l"(p));
    return a;
}
__device__ __forceinline__ void ldmx4(uint32_t &r0, uint32_t &r1, uint32_t &r2, uint32_t &r3, uint32_t a){
    asm volatile("ldmatrix.sync.aligned.m8n8.x4.shared.b16 {%0,%1,%2,%3}, [%4];"
        : "=r"(r0), "=r"(r1), "=r"(r2), "=r"(r3) : "r"(a));
}
__device__ __forceinline__ void mma16816(float* c, const uint32_t* a, const uint32_t* b){
    asm volatile("mma.sync.aligned.m16n8k16.row.col.f32.f16.f16.f32 "
        "{%0,%1,%2,%3}, {%4,%5,%6,%7}, {%8,%9}, {%0,%1,%2,%3};"
        : "+f"(c[0]), "+f"(c[1]), "+f"(c[2]), "+f"(c[3])
        : "r"(a[0]), "r"(a[1]), "r"(a[2]), "r"(a[3]), "r"(b[0]), "r"(b[1]));
}
__device__ __forceinline__ void red_v4(float* gptr, float x, float y, float z, float w){
    asm volatile("red.global.add.v4.f32 [%0], {%1,%2,%3,%4};"
        :: "l"(__cvta_generic_to_global(gptr)), "f"(x), "f"(y), "f"(z), "f"(w) : "memory");
}
__device__ __forceinline__ void red_s(float* gptr, float x){
    asm volatile("red.global.add.f32 [%0], %1;"
        :: "l"(__cvta_generic_to_global(gptr)), "f"(x) : "memory");
}
__device__ __forceinline__ void cp_async16(uint32_t dst, const void* src){
    asm volatile("cp.async.ca.shared.global [%0], [%1], 16;"
        :: "r"(dst), "l"(__cvta_generic_to_global(src)) : "memory");
}
__device__ __forceinline__ uint32_t pack_half2(float a, float b){
    __half h0 = __float2half(a), h1 = __float2half(b);
    return (uint32_t)__half_as_ushort(h0) | ((uint32_t)__half_as_ushort(h1) << 16);
}

// ---------------- zero scratch ----------------
__global__ void k_zero(){
    size_t stride = (size_t)gridDim.x * blockDim.x;
    size_t t0 = (size_t)blockIdx.x * blockDim.x + threadIdx.x;
    for(size_t i = t0; i < (size_t)BB*R3*CIN; i += stride) g_acc[i] = 0.f;
    for(size_t i = t0; i < (size_t)BB*R3; i += stride) g_cnt[i] = 0.f;
}

// ---------------- per-batch mean ----------------
__global__ void k_mean(const float* __restrict__ coords){
    __shared__ float sh[256];
    int b = blockIdx.x, tid = threadIdx.x;
    for(int a = 0; a < 3; a++){
        float s = 0.f;
        for(int n = tid; n < NPTS; n += 256) s += coords[((size_t)b*3 + a)*NPTS + n];
        sh[tid] = s; __syncthreads();
        for(int off = 128; off; off >>= 1){ if(tid < off) sh[tid] += sh[tid+off]; __syncthreads(); }
        if(tid == 0) g_mean[b*3 + a] = sh[0] / (float)NPTS;
        __syncthreads();
    }
}

// ---------------- per-batch max radius -> scale ----------------
__global__ void k_radius(const float* __restrict__ coords){
    __shared__ float sh[256];
    int b = blockIdx.x, tid = threadIdx.x;
    float m0 = g_mean[b*3+0], m1 = g_mean[b*3+1], m2 = g_mean[b*3+2];
    float mx = 0.f;
    for(int n = tid; n < NPTS; n += 256){
        float dx = coords[((size_t)b*3+0)*NPTS + n] - m0;
        float dy = coords[((size_t)b*3+1)*NPTS + n] - m1;
        float dz = coords[((size_t)b*3+2)*NPTS + n] - m2;
        mx = fmaxf(mx, dx*dx + dy*dy + dz*dz);
    }
    sh[tid] = mx; __syncthreads();
    for(int off = 128; off; off >>= 1){ if(tid < off) sh[tid] = fmaxf(sh[tid], sh[tid+off]); __syncthreads(); }
    if(tid == 0) g_scale[b] = 1.0f / (2.0f * sqrtf(sh[0]) * (1.0f + 1e-6f));
}

// ---------------- transpose features [b][c][n] -> [b][n][c] ----------------
__global__ void k_tfeat(const float* __restrict__ f){
    __shared__ float s[32][33];
    int b = blockIdx.z;
    int n = blockIdx.x*32 + threadIdx.x;
    int cbase = blockIdx.y*32;
    #pragma unroll
    for(int j = 0; j < 4; j++){
        int c = cbase + threadIdx.y + j*8;
        s[threadIdx.y + j*8][threadIdx.x] = f[((size_t)b*CIN + c)*NPTS + n];
    }
    __syncthreads();
    int c2 = cbase + threadIdx.x;
    #pragma unroll
    for(int j = 0; j < 4; j++){
        int n2 = blockIdx.x*32 + threadIdx.y + j*8;
        g_featT[((size_t)b*NPTS + n2)*CIN + c2] = s[threadIdx.x][threadIdx.y + j*8];
    }
}

// ---------------- weight prep: w[co][ci][tap] -> fp16 [which*27+tap][co][ci] ----------------
__global__ void k_prepw(const float* __restrict__ w1, const float* __restrict__ w2){
    int idx = blockIdx.x*256 + threadIdx.x;   // 2*27*4096 = 221184
    if(idx >= 221184) return;
    int which = idx / 110592;
    int r = idx - which*110592;
    int tap = r >> 12;
    int co  = (r >> 6) & 63;
    int ci  = r & 63;
    const float* src = which ? w2 : w1;
    g_wh[(which*27 + tap)*4096 + co*64 + ci] = __float2half(src[(co*64 + ci)*27 + tap]);
}

// ---------------- trilinear scatter (vector reductions) ----------------
__global__ void k_scatter(const float* __restrict__ coords){
    int t = blockIdx.x*256 + threadIdx.x;     // BB*NPTS*16 threads
    int c4 = t & 15;
    int p = t >> 4;
    int b = p >> 15;
    int n = p & (NPTS-1);
    float sc = g_scale[b];
    float vx = fminf(fmaxf(((coords[((size_t)b*3+0)*NPTS+n] - g_mean[b*3+0])*sc + 0.5f)*32.f, 0.f), 31.f);
    float vy = fminf(fmaxf(((coords[((size_t)b*3+1)*NPTS+n] - g_mean[b*3+1])*sc + 0.5f)*32.f, 0.f), 31.f);
    float vz = fminf(fmaxf(((coords[((size_t)b*3+2)*NPTS+n] - g_mean[b*3+2])*sc + 0.5f)*32.f, 0.f), 31.f);
    int lx = (int)floorf(vx), ly = (int)floorf(vy), lz = (int)floorf(vz);
    float fx = vx - lx, fy = vy - ly, fz = vz - lz;
    float4 f = *(const float4*)(g_featT + (size_t)p*64 + c4*4);
    #pragma unroll
    for(int corner = 0; corner < 8; corner++){
        int dxb = corner >> 2, dyb = (corner >> 1) & 1, dzb = corner & 1;
        int xi = min(lx + dxb, 31), yi = min(ly + dyb, 31), zi = min(lz + dzb, 31);
        float w = (dxb ? fx : 1.f-fx) * (dyb ? fy : 1.f-fy) * (dzb ? fz : 1.f-fz);
        int vi = (xi*32 + yi)*32 + zi;
        float* base = g_acc + ((size_t)b*R3 + vi)*64 + c4*4;
        red_v4(base, w*f.x, w*f.y, w*f.z, w*f.w);
        if(c4 == 0) red_s(&g_cnt[b*R3 + vi], w);
    }
}

// ---------------- HMMA conv: 3x3x3, 64->64, fp16 1-pass, M=256 tile, BN + leaky ----------------
// smem: A @0 (93312 = 648 rows * 144B), W0 @93312 (9216), W1 @102528 (9216)
#define SM_W0 93312
#define SM_W1 102528
#define CONV_SMEM 111744

__global__ void __launch_bounds__(256, 2) k_conv_mma(int mode,
        const float* __restrict__ cb, const float* __restrict__ bg,
        const float* __restrict__ bb, const float* __restrict__ bm,
        const float* __restrict__ bv){
    extern __shared__ char sm[];
    __shared__ float s_scale[64], s_bias[64];

    const __half* __restrict__ Wg = g_wh + (size_t)mode*27*4096;

    int tid = threadIdx.x;
    int cta = blockIdx.x;                  // 1024 = 8b * 8x * 8y * 2z
    int b  = cta >> 7; int rem = cta & 127;
    int x0 = (rem >> 4)*4;
    int y0 = ((rem >> 1) & 7)*4;
    int z0 = (rem & 1)*16;
    uint32_t sb = smem_u32(sm);

    // prefetch W(0) into W0 (64 rows x 8 chunks of 16B)
    #pragma unroll
    for(int k = 0; k < 2; k++){
        int ch = k*256 + tid;
        int co = ch >> 3, cg = ch & 7;
        cp_async16(sb + SM_W0 + co*144 + cg*16, Wg + co*64 + cg*8);
    }
    asm volatile("cp.async.commit_group;" ::: "memory");

    if(tid < 64){
        float s = bg[tid] * rsqrtf(bv[tid] + 1e-4f);
        s_scale[tid] = s;
        s_bias[tid]  = (cb[tid] - bm[tid]) * s + bb[tid];
    }

    // ---- load halo 6x6x18 x 64ci fp16, row pitch 144B ----
    if(mode == 0){
        // fused: read fp32 accumulator + count, normalize, convert to fp16
        for(int i = tid; i < 5184; i += 256){
            int hv = i >> 3, cg = i & 7;
            int hx = hv/108; int r = hv - hx*108; int hy = r/18; int hz = r - hy*18;
            int gx = x0 - 1 + hx, gy = y0 - 1 + hy, gz = z0 - 1 + hz;
            uint4 vh = make_uint4(0,0,0,0);
            if((unsigned)gx < 32u && (unsigned)gy < 32u && (unsigned)gz < 32u){
                size_t vidx = (((size_t)b*32 + gx)*32 + gy)*32 + gz;
                float inv = 1.0f / fmaxf(g_cnt[vidx], 1e-8f);
                const float4* src = (const float4*)(g_acc + vidx*64 + cg*8);
                float4 p0 = src[0], p1 = src[1];
                vh.x = pack_half2(p0.x*inv, p0.y*inv);
                vh.y = pack_half2(p0.z*inv, p0.w*inv);
                vh.z = pack_half2(p1.x*inv, p1.y*inv);
                vh.w = pack_half2(p1.z*inv, p1.w*inv);
            }
            *(uint4*)(sm + hv*144 + cg*16) = vh;
        }
    } else {
        for(int i = tid; i < 5184; i += 256){
            int hv = i >> 3, cg = i & 7;
            int hx = hv/108; int r = hv - hx*108; int hy = r/18; int hz = r - hy*18;
            int gx = x0 - 1 + hx, gy = y0 - 1 + hy, gz = z0 - 1 + hz;
            uint4 vh = make_uint4(0,0,0,0);
            if((unsigned)gx < 32u && (unsigned)gy < 32u && (unsigned)gz < 32u){
                size_t gidx = ((((size_t)b*32 + gx)*32 + gy)*32 + gz)*64 + cg*8;
                vh = *(const uint4*)(g_v1h + gidx);
            }
            *(uint4*)(sm + hv*144 + cg*16) = vh;
        }
    }

    // ---- per-lane fragment addressing ----
    int lane = tid & 31, wrp = tid >> 5;
    int rr = lane & 15, kh = lane >> 4;
    int vxw = wrp >> 1;                    // voxel x (tile-local, 0..3)
    int vy0 = (wrp*2) & 3, vy1 = (wrp*2 + 1) & 3;
    int tl = lane >> 3, lr = lane & 7;
    uint32_t w_lane = (uint32_t)((((tl>>1)*8 + lr)*144) + (tl&1)*16);

    float C[2][8][4];
    #pragma unroll
    for(int t = 0; t < 2; t++)
        #pragma unroll
        for(int g = 0; g < 8; g++){ C[t][g][0]=0.f; C[t][g][1]=0.f; C[t][g][2]=0.f; C[t][g][3]=0.f; }

    for(int tap = 0; tap < 27; tap++){
        asm volatile("cp.async.wait_group 0;" ::: "memory");
        __syncthreads();
        if(tap < 26){
            uint32_t nb = ((tap+1) & 1) ? SM_W1 : SM_W0;
            #pragma unroll
            for(int k = 0; k < 2; k++){
                int ch = k*256 + tid;
                int co = ch >> 3, cg = ch & 7;
                cp_async16(sb + nb + co*144 + cg*16,
                           Wg + (size_t)(tap+1)*4096 + co*64 + cg*8);
            }
            asm volatile("cp.async.commit_group;" ::: "memory");
        }

        uint32_t wb = (tap & 1) ? SM_W1 : SM_W0;
        uint32_t whb = sb + wb + w_lane;

        int dx = tap/9, rem2 = tap - 9*dx;
        int dy = rem2/3, dz = rem2 - 3*dy;
        uint32_t a0 = sb + (uint32_t)((((vxw+dx)*6 + (vy0+dy))*18 + (rr+dz))*144) + kh*16;
        uint32_t a1 = sb + (uint32_t)((((vxw+dx)*6 + (vy1+dy))*18 + (rr+dz))*144) + kh*16;

        #pragma unroll
        for(int kc = 0; kc < 4; kc++){
            uint32_t ah0[4], ah1[4];
            uint32_t bw[4][4];
            ldmx4(ah0[0], ah0[1], ah0[2], ah0[3], a0 + kc*32);
            ldmx4(ah1[0], ah1[1], ah1[2], ah1[3], a1 + kc*32);
            #pragma unroll
            for(int j = 0; j < 4; j++)
                ldmx4(bw[j][0], bw[j][1], bw[j][2], bw[j][3], whb + j*2304 + kc*32);
            #pragma unroll
            for(int j = 0; j < 4; j++){
                mma16816(C[0][2*j],   ah0, &bw[j][0]);
                mma16816(C[0][2*j+1], ah0, &bw[j][2]);
                mma16816(C[1][2*j],   ah1, &bw[j][0]);
                mma16816(C[1][2*j+1], ah1, &bw[j][2]);
            }
        }
    }

    // ---- epilogue: BN + leaky, store ----
    int tr = lane >> 2, c2 = (lane & 3)*2;
    #pragma unroll
    for(int t = 0; t < 2; t++){
        #pragma unroll
        for(int half = 0; half < 2; half++){
            int mm = wrp*32 + t*16 + half*8 + tr;
            int xg = x0 + (mm >> 6), yg = y0 + ((mm >> 4) & 3), zg = z0 + (mm & 15);
            size_t vbase = ((((size_t)b*32 + xg)*32 + yg)*32 + zg)*64;
            #pragma unroll
            for(int g = 0; g < 8; g++){
                int co = g*8 + c2;
                float y0v = C[t][g][half*2+0]*s_scale[co]   + s_bias[co];
                float y1v = C[t][g][half*2+1]*s_scale[co+1] + s_bias[co+1];
                y0v = (y0v > 0.f) ? y0v : 0.1f*y0v;
                y1v = (y1v > 0.f) ? y1v : 0.1f*y1v;
                if(mode){
                    float2 st; st.x = y0v; st.y = y1v;
                    *(float2*)(g_vox2 + vbase + co) = st;
                } else {
                    *(uint32_t*)((__half*)g_v1h + vbase + co) = pack_half2(y0v, y1v);
                }
            }
        }
    }
}

// ---------------- devoxelize (coalesced gather) + point-branch MLP ----------------
#define DEVOX_SMEM 54784

__global__ void __launch_bounds__(128) k_devox(const float* __restrict__ coords,
        const float* __restrict__ mlpw, const float* __restrict__ mlpb,
        const float* __restrict__ bg, const float* __restrict__ bb,
        const float* __restrict__ bm, const float* __restrict__ bv,
        float* __restrict__ outp){
    extern __shared__ char dsm[];
    float* s_mw    = (float*)dsm;                 // [ci][co] 64x64
    float* s_out   = (float*)(dsm + 16384);       // per warp 64*33
    float* s_f     = (float*)(dsm + 50176);       // per warp 4*64
    float* s_scale = (float*)(dsm + 54272);
    float* s_bias  = (float*)(dsm + 54528);

    int tid = threadIdx.x, lane = tid & 31, w = tid >> 5;
    int b = blockIdx.x >> 8;
    int n_base = (blockIdx.x & 255) * 128;

    for(int i = tid; i < 4096; i += 128){ int co = i >> 6, ci = i & 63; s_mw[ci*64 + co] = mlpw[i]; }
    if(tid < 64){
        float s = bg[tid] * rsqrtf(bv[tid] + 1e-4f);
        s_scale[tid] = s;
        s_bias[tid]  = (mlpb[tid] - bm[tid]) * s + bb[tid];
    }
    __syncthreads();

    float* my_out = s_out + w*2112;
    float* my_f   = s_f + w*256;
    int n0 = n_base + w*32;
    float s0 = s_scale[2*lane], s1 = s_scale[2*lane+1];
    float bi0 = s_bias[2*lane], bi1 = s_bias[2*lane+1];
    float scb = g_scale[b];
    float m0c = g_mean[b*3+0], m1c = g_mean[b*3+1], m2c = g_mean[b*3+2];

    for(int pg = 0; pg < 8; pg++){
        int n = n0 + pg*4;
        #pragma unroll
        for(int q = 0; q < 4; q++){
            float2 f2 = *(const float2*)(g_featT + ((size_t)b*NPTS + n + q)*64 + 2*lane);
            *(float2*)(my_f + q*64 + 2*lane) = f2;
        }
        __syncwarp();
        float a[4][2];
        #pragma unroll
        for(int q = 0; q < 4; q++){ a[q][0] = 0.f; a[q][1] = 0.f; }
        #pragma unroll 8
        for(int ci = 0; ci < 64; ci++){
            float2 wv = *(const float2*)(s_mw + ci*64 + 2*lane);
            #pragma unroll
            for(int q = 0; q < 4; q++){
                float f = my_f[q*64 + ci];
                a[q][0] += f*wv.x; a[q][1] += f*wv.y;
            }
        }
        #pragma unroll
        for(int q = 0; q < 4; q++){
            int n_ = n + q;
            float r0 = fmaxf(a[q][0]*s0 + bi0, 0.f);
            float r1 = fmaxf(a[q][1]*s1 + bi1, 0.f);
            float vx = fminf(fmaxf(((coords[((size_t)b*3+0)*NPTS+n_] - m0c)*scb + 0.5f)*32.f, 0.f), 31.f);
            float vy = fminf(fmaxf(((coords[((size_t)b*3+1)*NPTS+n_] - m1c)*scb + 0.5f)*32.f, 0.f), 31.f);
            float vz = fminf(fmaxf(((coords[((size_t)b*3+2)*NPTS+n_] - m2c)*scb + 0.5f)*32.f, 0.f), 31.f);
            int lx = (int)floorf(vx), ly = (int)floorf(vy), lz = (int)floorf(vz);
            float fx = vx - lx, fy = vy - ly, fz = vz - lz;
            #pragma unroll
            for(int corner = 0; corner < 8; corner++){
                int dxb = corner >> 2, dyb = (corner >> 1) & 1, dzb = corner & 1;
                int xi = min(lx+dxb,31), yi = min(ly+dyb,31), zi = min(lz+dzb,31);
                float wgt = (dxb ? fx : 1.f-fx) * (dyb ? fy : 1.f-fy) * (dzb ? fz : 1.f-fz);
                int vi = (xi*32 + yi)*32 + zi;
                float2 v = *(const float2*)(g_vox2 + ((size_t)b*R3 + vi)*64 + 2*lane);
                r0 += wgt*v.x; r1 += wgt*v.y;
            }
            my_out[(2*lane)*33   + pg*4 + q] = r0;
            my_out[(2*lane+1)*33 + pg*4 + q] = r1;
        }
    }
    __syncwarp();
    for(int r = 0; r < 64; r++)
        outp[((size_t)b*64 + r)*NPTS + n0 + lane] = my_out[r*33 + lane];
}

// ---------------- copy coords ----------------
__global__ void k_copy(const float* __restrict__ coords, float* __restrict__ dst){
    int i = blockIdx.x*256 + threadIdx.x;
    if(i < BB*3*NPTS) dst[i] = coords[i];
}

// ---------------- launch ----------------
extern "C" void kernel_launch(void* const* d_in, const int* in_sizes, int n_in,
                              void* d_out, int out_size){
    const float* features = (const float*)d_in[0];
    const float* coords   = (const float*)d_in[1];
    const float* c1w = (const float*)d_in[2];
    const float* c1b = (const float*)d_in[3];
    const float* b1g = (const float*)d_in[4];
    const float* b1b = (const float*)d_in[5];
    const float* b1m = (const float*)d_in[6];
    const float* b1v = (const float*)d_in[7];
    const float* c2w = (const float*)d_in[8];
    const float* c2b = (const float*)d_in[9];
    const float* b2g = (const float*)d_in[10];
    const float* b2b = (const float*)d_in[11];
    const float* b2m = (const float*)d_in[12];
    const float* b2v = (const float*)d_in[13];
    const float* mw  = (const float*)d_in[14];
    const float* mb  = (const float*)d_in[15];
    const float* bpg = (const float*)d_in[16];
    const float* bpb = (const float*)d_in[17];
    const float* bpm = (const float*)d_in[18];
    const float* bpv = (const float*)d_in[19];
    float* out = (float*)d_out;

    cudaFuncSetAttribute(k_conv_mma, cudaFuncAttributeMaxDynamicSharedMemorySize, CONV_SMEM);
    cudaFuncSetAttribute(k_devox, cudaFuncAttributeMaxDynamicSharedMemorySize, DEVOX_SMEM);

    k_zero   <<<2048, 256>>>();
    k_mean   <<<BB,   256>>>(coords);
    k_radius <<<BB,   256>>>(coords);
    k_tfeat  <<<dim3(NPTS/32, CIN/32, BB), dim3(32, 8)>>>(features);
    k_prepw  <<<(221184 + 255)/256, 256>>>(c1w, c2w);
    k_scatter<<<(BB*NPTS*16)/256, 256>>>(coords);
    k_conv_mma<<<1024, 256, CONV_SMEM>>>(0, c1b, b1g, b1b, b1m, b1v);
    k_conv_mma<<<1024, 256, CONV_SMEM>>>(1, c2b, b2g, b2b, b2m, b2v);
    k_devox  <<<2048, 128, DEVOX_SMEM>>>(coords, mw, mb, bpg, bpb, bpm, bpv, out);
    k_copy   <<<(BB*3*NPTS + 255)/256, 256>>>(coords, out + (size_t)BB*COUT*NPTS);
}

// round 8
// speedup vs baseline: 1.4359x; 1.4359x over previous
#include <cuda_runtime.h>
#include <cuda_fp16.h>
#include <math.h>
#include <stdint.h>

#define BB    8
#define CIN   64
#define COUT  64
#define NPTS  32768
#define R3    32768

// ---------------- scratch (static __device__ — no allocations) ----------------
__device__ float g_featT[(size_t)BB*NPTS*CIN];            // [b][n][c]
__device__ float g_acc  [(size_t)BB*R3*CIN];              // [b][x][y][z][c]
__device__ float g_cnt  [BB*R3];
__device__ __half g_v1h[(size_t)BB*R3*COUT];              // conv1 out fp16 [b][x][y][z][c]
__device__ __half g_vox2[(size_t)BB*R3*COUT];             // conv2 out fp16 [b][x][y][z][c]
__device__ __half g_wh [2*27*64*64];                      // [which*27 + tap][co][ci]  fp16
__device__ float g_mean [BB*3];
__device__ float g_scale[BB];

// ---------------- helpers ----------------
__device__ __forceinline__ uint32_t smem_u32(const void* p){
    uint32_t a;
    asm("{ .reg .u64 t; cvta.to.shared.u64 t, %1; cvt.u32.u64 %0, t; }" : "=r"(a) : "l"(p));
    return a;
}
__device__ __forceinline__ void ldmx4(uint32_t &r0, uint32_t &r1, uint32_t &r2, uint32_t &r3, uint32_t a){
    asm volatile("ldmatrix.sync.aligned.m8n8.x4.shared.b16 {%0,%1,%2,%3}, [%4];"
        : "=r"(r0), "=r"(r1), "=r"(r2), "=r"(r3) : "r"(a));
}
__device__ __forceinline__ void mma16816(float* c, const uint32_t* a, const uint32_t* b){
    asm volatile("mma.sync.aligned.m16n8k16.row.col.f32.f16.f16.f32 "
        "{%0,%1,%2,%3}, {%4,%5,%6,%7}, {%8,%9}, {%0,%1,%2,%3};"
        : "+f"(c[0]), "+f"(c[1]), "+f"(c[2]), "+f"(c[3])
        : "r"(a[0]), "r"(a[1]), "r"(a[2]), "r"(a[3]), "r"(b[0]), "r"(b[1]));
}
__device__ __forceinline__ void red_v4(float* gptr, float x, float y, float z, float w){
    asm volatile("red.global.add.v4.f32 [%0], {%1,%2,%3,%4};"
        :: "l"(__cvta_generic_to_global(gptr)), "f"(x), "f"(y), "f"(z), "f"(w) : "memory");
}
__device__ __forceinline__ void red_s(float* gptr, float x){
    asm volatile("red.global.add.f32 [%0], %1;"
        :: "l"(__cvta_generic_to_global(gptr)), "f"(x) : "memory");
}
__device__ __forceinline__ void cp_async16(uint32_t dst, const void* src){
    asm volatile("cp.async.ca.shared.global [%0], [%1], 16;"
        :: "r"(dst), "l"(__cvta_generic_to_global(src)) : "memory");
}
__device__ __forceinline__ uint32_t pack_half2(float a, float b){
    __half h0 = __float2half(a), h1 = __float2half(b);
    return (uint32_t)__half_as_ushort(h0) | ((uint32_t)__half_as_ushort(h1) << 16);
}

// ---------------- zero scratch (vectorized) ----------------
__global__ void k_zero(){
    size_t stride = (size_t)gridDim.x * blockDim.x;
    size_t t0 = (size_t)blockIdx.x * blockDim.x + threadIdx.x;
    float4 z = make_float4(0.f, 0.f, 0.f, 0.f);
    for(size_t i = t0; i < (size_t)BB*R3*CIN/4; i += stride) ((float4*)g_acc)[i] = z;
    for(size_t i = t0; i < (size_t)BB*R3/4; i += stride) ((float4*)g_cnt)[i] = z;
}

// ---------------- per-batch mean ----------------
__global__ void k_mean(const float* __restrict__ coords){
    __shared__ float sh[256];
    int b = blockIdx.x, tid = threadIdx.x;
    for(int a = 0; a < 3; a++){
        float s = 0.f;
        for(int n = tid; n < NPTS; n += 256) s += coords[((size_t)b*3 + a)*NPTS + n];
        sh[tid] = s; __syncthreads();
        for(int off = 128; off; off >>= 1){ if(tid < off) sh[tid] += sh[tid+off]; __syncthreads(); }
        if(tid == 0) g_mean[b*3 + a] = sh[0] / (float)NPTS;
        __syncthreads();
    }
}

// ---------------- per-batch max radius -> scale ----------------
__global__ void k_radius(const float* __restrict__ coords){
    __shared__ float sh[256];
    int b = blockIdx.x, tid = threadIdx.x;
    float m0 = g_mean[b*3+0], m1 = g_mean[b*3+1], m2 = g_mean[b*3+2];
    float mx = 0.f;
    for(int n = tid; n < NPTS; n += 256){
        float dx = coords[((size_t)b*3+0)*NPTS + n] - m0;
        float dy = coords[((size_t)b*3+1)*NPTS + n] - m1;
        float dz = coords[((size_t)b*3+2)*NPTS + n] - m2;
        mx = fmaxf(mx, dx*dx + dy*dy + dz*dz);
    }
    sh[tid] = mx; __syncthreads();
    for(int off = 128; off; off >>= 1){ if(tid < off) sh[tid] = fmaxf(sh[tid], sh[tid+off]); __syncthreads(); }
    if(tid == 0) g_scale[b] = 1.0f / (2.0f * sqrtf(sh[0]) * (1.0f + 1e-6f));
}

// ---------------- transpose features [b][c][n] -> [b][n][c] ----------------
__global__ void k_tfeat(const float* __restrict__ f){
    __shared__ float s[32][33];
    int b = blockIdx.z;
    int n = blockIdx.x*32 + threadIdx.x;
    int cbase = blockIdx.y*32;
    #pragma unroll
    for(int j = 0; j < 4; j++){
        int c = cbase + threadIdx.y + j*8;
        s[threadIdx.y + j*8][threadIdx.x] = f[((size_t)b*CIN + c)*NPTS + n];
    }
    __syncthreads();
    int c2 = cbase + threadIdx.x;
    #pragma unroll
    for(int j = 0; j < 4; j++){
        int n2 = blockIdx.x*32 + threadIdx.y + j*8;
        g_featT[((size_t)b*NPTS + n2)*CIN + c2] = s[threadIdx.x][threadIdx.y + j*8];
    }
}

// ---------------- weight prep: w[co][ci][tap] -> fp16 [which*27+tap][co][ci] ----------------
__global__ void k_prepw(const float* __restrict__ w1, const float* __restrict__ w2){
    int idx = blockIdx.x*256 + threadIdx.x;   // 2*27*4096 = 221184
    if(idx >= 221184) return;
    int which = idx / 110592;
    int r = idx - which*110592;
    int tap = r >> 12;
    int co  = (r >> 6) & 63;
    int ci  = r & 63;
    const float* src = which ? w2 : w1;
    g_wh[(which*27 + tap)*4096 + co*64 + ci] = __float2half(src[(co*64 + ci)*27 + tap]);
}

// ---------------- trilinear scatter (vector reductions) ----------------
__global__ void k_scatter(const float* __restrict__ coords){
    int t = blockIdx.x*256 + threadIdx.x;     // BB*NPTS*16 threads
    int c4 = t & 15;
    int p = t >> 4;
    int b = p >> 15;
    int n = p & (NPTS-1);
    float sc = g_scale[b];
    float vx = fminf(fmaxf(((coords[((size_t)b*3+0)*NPTS+n] - g_mean[b*3+0])*sc + 0.5f)*32.f, 0.f), 31.f);
    float vy = fminf(fmaxf(((coords[((size_t)b*3+1)*NPTS+n] - g_mean[b*3+1])*sc + 0.5f)*32.f, 0.f), 31.f);
    float vz = fminf(fmaxf(((coords[((size_t)b*3+2)*NPTS+n] - g_mean[b*3+2])*sc + 0.5f)*32.f, 0.f), 31.f);
    int lx = (int)floorf(vx), ly = (int)floorf(vy), lz = (int)floorf(vz);
    float fx = vx - lx, fy = vy - ly, fz = vz - lz;
    float4 f = *(const float4*)(g_featT + (size_t)p*64 + c4*4);
    #pragma unroll
    for(int corner = 0; corner < 8; corner++){
        int dxb = corner >> 2, dyb = (corner >> 1) & 1, dzb = corner & 1;
        int xi = min(lx + dxb, 31), yi = min(ly + dyb, 31), zi = min(lz + dzb, 31);
        float w = (dxb ? fx : 1.f-fx) * (dyb ? fy : 1.f-fy) * (dzb ? fz : 1.f-fz);
        int vi = (xi*32 + yi)*32 + zi;
        float* base = g_acc + ((size_t)b*R3 + vi)*64 + c4*4;
        red_v4(base, w*f.x, w*f.y, w*f.z, w*f.w);
        if(c4 == 0) red_s(&g_cnt[b*R3 + vi], w);
    }
}

// ---------------- HMMA conv: 3x3x3, 64->64, fp16 1-pass, M=256 tile, BN + leaky ----------------
// smem: A @0 (93312 = 648 rows * 144B), W0 @93312 (9216), W1 @102528 (9216)
#define SM_W0 93312
#define SM_W1 102528
#define CONV_SMEM 111744

__global__ void __launch_bounds__(256, 2) k_conv_mma(int mode,
        const float* __restrict__ cb, const float* __restrict__ bg,
        const float* __restrict__ bb, const float* __restrict__ bm,
        const float* __restrict__ bv){
    extern __shared__ char sm[];
    __shared__ float s_scale[64], s_bias[64];

    const __half* __restrict__ Wg = g_wh + (size_t)mode*27*4096;

    int tid = threadIdx.x;
    int cta = blockIdx.x;                  // 1024 = 8b * 8x * 8y * 2z
    int b  = cta >> 7; int rem = cta & 127;
    int x0 = (rem >> 4)*4;
    int y0 = ((rem >> 1) & 7)*4;
    int z0 = (rem & 1)*16;
    uint32_t sb = smem_u32(sm);

    // prefetch W(0) into W0 (64 rows x 8 chunks of 16B)
    #pragma unroll
    for(int k = 0; k < 2; k++){
        int ch = k*256 + tid;
        int co = ch >> 3, cg = ch & 7;
        cp_async16(sb + SM_W0 + co*144 + cg*16, Wg + co*64 + cg*8);
    }
    asm volatile("cp.async.commit_group;" ::: "memory");

    if(tid < 64){
        float s = bg[tid] * rsqrtf(bv[tid] + 1e-4f);
        s_scale[tid] = s;
        s_bias[tid]  = (cb[tid] - bm[tid]) * s + bb[tid];
    }

    // ---- load halo 6x6x18 x 64ci fp16, row pitch 144B ----
    if(mode == 0){
        // fused: read fp32 accumulator + count, normalize, convert to fp16
        for(int i = tid; i < 5184; i += 256){
            int hv = i >> 3, cg = i & 7;
            int hx = hv/108; int r = hv - hx*108; int hy = r/18; int hz = r - hy*18;
            int gx = x0 - 1 + hx, gy = y0 - 1 + hy, gz = z0 - 1 + hz;
            uint4 vh = make_uint4(0,0,0,0);
            if((unsigned)gx < 32u && (unsigned)gy < 32u && (unsigned)gz < 32u){
                size_t vidx = (((size_t)b*32 + gx)*32 + gy)*32 + gz;
                float inv = 1.0f / fmaxf(g_cnt[vidx], 1e-8f);
                const float4* src = (const float4*)(g_acc + vidx*64 + cg*8);
                float4 p0 = src[0], p1 = src[1];
                vh.x = pack_half2(p0.x*inv, p0.y*inv);
                vh.y = pack_half2(p0.z*inv, p0.w*inv);
                vh.z = pack_half2(p1.x*inv, p1.y*inv);
                vh.w = pack_half2(p1.z*inv, p1.w*inv);
            }
            *(uint4*)(sm + hv*144 + cg*16) = vh;
        }
    } else {
        for(int i = tid; i < 5184; i += 256){
            int hv = i >> 3, cg = i & 7;
            int hx = hv/108; int r = hv - hx*108; int hy = r/18; int hz = r - hy*18;
            int gx = x0 - 1 + hx, gy = y0 - 1 + hy, gz = z0 - 1 + hz;
            uint4 vh = make_uint4(0,0,0,0);
            if((unsigned)gx < 32u && (unsigned)gy < 32u && (unsigned)gz < 32u){
                size_t gidx = ((((size_t)b*32 + gx)*32 + gy)*32 + gz)*64 + cg*8;
                vh = *(const uint4*)(g_v1h + gidx);
            }
            *(uint4*)(sm + hv*144 + cg*16) = vh;
        }
    }

    // ---- per-lane fragment addressing ----
    int lane = tid & 31, wrp = tid >> 5;
    int rr = lane & 15, kh = lane >> 4;
    int vxw = wrp >> 1;                    // voxel x (tile-local, 0..3)
    int vy0 = (wrp*2) & 3, vy1 = (wrp*2 + 1) & 3;
    int tl = lane >> 3, lr = lane & 7;
    uint32_t w_lane = (uint32_t)((((tl>>1)*8 + lr)*144) + (tl&1)*16);

    float C[2][8][4];
    #pragma unroll
    for(int t = 0; t < 2; t++)
        #pragma unroll
        for(int g = 0; g < 8; g++){ C[t][g][0]=0.f; C[t][g][1]=0.f; C[t][g][2]=0.f; C[t][g][3]=0.f; }

    for(int tap = 0; tap < 27; tap++){
        asm volatile("cp.async.wait_group 0;" ::: "memory");
        __syncthreads();
        if(tap < 26){
            uint32_t nb = ((tap+1) & 1) ? SM_W1 : SM_W0;
            #pragma unroll
            for(int k = 0; k < 2; k++){
                int ch = k*256 + tid;
                int co = ch >> 3, cg = ch & 7;
                cp_async16(sb + nb + co*144 + cg*16,
                           Wg + (size_t)(tap+1)*4096 + co*64 + cg*8);
            }
            asm volatile("cp.async.commit_group;" ::: "memory");
        }

        uint32_t wb = (tap & 1) ? SM_W1 : SM_W0;
        uint32_t whb = sb + wb + w_lane;

        int dx = tap/9, rem2 = tap - 9*dx;
        int dy = rem2/3, dz = rem2 - 3*dy;
        uint32_t a0 = sb + (uint32_t)((((vxw+dx)*6 + (vy0+dy))*18 + (rr+dz))*144) + kh*16;
        uint32_t a1 = sb + (uint32_t)((((vxw+dx)*6 + (vy1+dy))*18 + (rr+dz))*144) + kh*16;

        #pragma unroll
        for(int kc = 0; kc < 4; kc++){
            uint32_t ah0[4], ah1[4];
            uint32_t bw[4][4];
            ldmx4(ah0[0], ah0[1], ah0[2], ah0[3], a0 + kc*32);
            ldmx4(ah1[0], ah1[1], ah1[2], ah1[3], a1 + kc*32);
            #pragma unroll
            for(int j = 0; j < 4; j++)
                ldmx4(bw[j][0], bw[j][1], bw[j][2], bw[j][3], whb + j*2304 + kc*32);
            #pragma unroll
            for(int j = 0; j < 4; j++){
                mma16816(C[0][2*j],   ah0, &bw[j][0]);
                mma16816(C[0][2*j+1], ah0, &bw[j][2]);
                mma16816(C[1][2*j],   ah1, &bw[j][0]);
                mma16816(C[1][2*j+1], ah1, &bw[j][2]);
            }
        }
    }

    // ---- epilogue: BN + leaky, store fp16 ----
    int tr = lane >> 2, c2 = (lane & 3)*2;
    __half* dst = mode ? g_vox2 : g_v1h;
    #pragma unroll
    for(int t = 0; t < 2; t++){
        #pragma unroll
        for(int half = 0; half < 2; half++){
            int mm = wrp*32 + t*16 + half*8 + tr;
            int xg = x0 + (mm >> 6), yg = y0 + ((mm >> 4) & 3), zg = z0 + (mm & 15);
            size_t vbase = ((((size_t)b*32 + xg)*32 + yg)*32 + zg)*64;
            #pragma unroll
            for(int g = 0; g < 8; g++){
                int co = g*8 + c2;
                float y0v = C[t][g][half*2+0]*s_scale[co]   + s_bias[co];
                float y1v = C[t][g][half*2+1]*s_scale[co+1] + s_bias[co+1];
                y0v = (y0v > 0.f) ? y0v : 0.1f*y0v;
                y1v = (y1v > 0.f) ? y1v : 0.1f*y1v;
                *(uint32_t*)(dst + vbase + co) = pack_half2(y0v, y1v);
            }
        }
    }
}

// ---------------- devoxelize (fp16 L2 gather) + point-branch MLP ----------------
#define DEVOX_SMEM 54784

__global__ void __launch_bounds__(128) k_devox(const float* __restrict__ coords,
        const float* __restrict__ mlpw, const float* __restrict__ mlpb,
        const float* __restrict__ bg, const float* __restrict__ bb,
        const float* __restrict__ bm, const float* __restrict__ bv,
        float* __restrict__ outp){
    extern __shared__ char dsm[];
    float* s_mw    = (float*)dsm;                 // [ci][co] 64x64
    float* s_out   = (float*)(dsm + 16384);       // per warp 64*33
    float* s_f     = (float*)(dsm + 50176);       // per warp 4*64
    float* s_scale = (float*)(dsm + 54272);
    float* s_bias  = (float*)(dsm + 54528);

    int tid = threadIdx.x, lane = tid & 31, w = tid >> 5;
    int b = blockIdx.x >> 8;
    int n_base = (blockIdx.x & 255) * 128;

    for(int i = tid; i < 4096; i += 128){ int co = i >> 6, ci = i & 63; s_mw[ci*64 + co] = mlpw[i]; }
    if(tid < 64){
        float s = bg[tid] * rsqrtf(bv[tid] + 1e-4f);
        s_scale[tid] = s;
        s_bias[tid]  = (mlpb[tid] - bm[tid]) * s + bb[tid];
    }
    __syncthreads();

    float* my_out = s_out + w*2112;
    float* my_f   = s_f + w*256;
    int n0 = n_base + w*32;
    float s0 = s_scale[2*lane], s1 = s_scale[2*lane+1];
    float bi0 = s_bias[2*lane], bi1 = s_bias[2*lane+1];
    float scb = g_scale[b];
    float m0c = g_mean[b*3+0], m1c = g_mean[b*3+1], m2c = g_mean[b*3+2];

    for(int pg = 0; pg < 8; pg++){
        int n = n0 + pg*4;
        #pragma unroll
        for(int q = 0; q < 4; q++){
            float2 f2 = *(const float2*)(g_featT + ((size_t)b*NPTS + n + q)*64 + 2*lane);
            *(float2*)(my_f + q*64 + 2*lane) = f2;
        }
        __syncwarp();
        float a[4][2];
        #pragma unroll
        for(int q = 0; q < 4; q++){ a[q][0] = 0.f; a[q][1] = 0.f; }
        #pragma unroll 8
        for(int ci = 0; ci < 64; ci++){
            float2 wv = *(const float2*)(s_mw + ci*64 + 2*lane);
            #pragma unroll
            for(int q = 0; q < 4; q++){
                float f = my_f[q*64 + ci];
                a[q][0] += f*wv.x; a[q][1] += f*wv.y;
            }
        }
        #pragma unroll
        for(int q = 0; q < 4; q++){
            int n_ = n + q;
            float r0 = fmaxf(a[q][0]*s0 + bi0, 0.f);
            float r1 = fmaxf(a[q][1]*s1 + bi1, 0.f);
            float vx = fminf(fmaxf(((coords[((size_t)b*3+0)*NPTS+n_] - m0c)*scb + 0.5f)*32.f, 0.f), 31.f);
            float vy = fminf(fmaxf(((coords[((size_t)b*3+1)*NPTS+n_] - m1c)*scb + 0.5f)*32.f, 0.f), 31.f);
            float vz = fminf(fmaxf(((coords[((size_t)b*3+2)*NPTS+n_] - m2c)*scb + 0.5f)*32.f, 0.f), 31.f);
            int lx = (int)floorf(vx), ly = (int)floorf(vy), lz = (int)floorf(vz);
            float fx = vx - lx, fy = vy - ly, fz = vz - lz;
            #pragma unroll
            for(int corner = 0; corner < 8; corner++){
                int dxb = corner >> 2, dyb = (corner >> 1) & 1, dzb = corner & 1;
                int xi = min(lx+dxb,31), yi = min(ly+dyb,31), zi = min(lz+dzb,31);
                float wgt = (dxb ? fx : 1.f-fx) * (dyb ? fy : 1.f-fy) * (dzb ? fz : 1.f-fz);
                int vi = (xi*32 + yi)*32 + zi;
                __half2 hv = *(const __half2*)(g_vox2 + ((size_t)b*R3 + vi)*64 + 2*lane);
                float2 v = __half22float2(hv);
                r0 += wgt*v.x; r1 += wgt*v.y;
            }
            my_out[(2*lane)*33   + pg*4 + q] = r0;
            my_out[(2*lane+1)*33 + pg*4 + q] = r1;
        }
    }
    __syncwarp();
    for(int r = 0; r < 64; r++)
        outp[((size_t)b*64 + r)*NPTS + n0 + lane] = my_out[r*33 + lane];
}

// ---------------- copy coords ----------------
__global__ void k_copy(const float* __restrict__ coords, float* __restrict__ dst){
    int i = blockIdx.x*256 + threadIdx.x;
    if(i < BB*3*NPTS) dst[i] = coords[i];
}

// ---------------- launch ----------------
extern "C" void kernel_launch(void* const* d_in, const int* in_sizes, int n_in,
                              void* d_out, int out_size){
    const float* features = (const float*)d_in[0];
    const float* coords   = (const float*)d_in[1];
    const float* c1w = (const float*)d_in[2];
    const float* c1b = (const float*)d_in[3];
    const float* b1g = (const float*)d_in[4];
    const float* b1b = (const float*)d_in[5];
    const float* b1m = (const float*)d_in[6];
    const float* b1v = (const float*)d_in[7];
    const float* c2w = (const float*)d_in[8];
    const float* c2b = (const float*)d_in[9];
    const float* b2g = (const float*)d_in[10];
    const float* b2b = (const float*)d_in[11];
    const float* b2m = (const float*)d_in[12];
    const float* b2v = (const float*)d_in[13];
    const float* mw  = (const float*)d_in[14];
    const float* mb  = (const float*)d_in[15];
    const float* bpg = (const float*)d_in[16];
    const float* bpb = (const float*)d_in[17];
    const float* bpm = (const float*)d_in[18];
    const float* bpv = (const float*)d_in[19];
    float* out = (float*)d_out;

    cudaFuncSetAttribute(k_conv_mma, cudaFuncAttributeMaxDynamicSharedMemorySize, CONV_SMEM);
    cudaFuncSetAttribute(k_devox, cudaFuncAttributeMaxDynamicSharedMemorySize, DEVOX_SMEM);

    k_zero   <<<2048, 256>>>();
    k_mean   <<<BB,   256>>>(coords);
    k_radius <<<BB,   256>>>(coords);
    k_tfeat  <<<dim3(NPTS/32, CIN/32, BB), dim3(32, 8)>>>(features);
    k_prepw  <<<(221184 + 255)/256, 256>>>(c1w, c2w);
    k_scatter<<<(BB*NPTS*16)/256, 256>>>(coords);
    k_conv_mma<<<1024, 256, CONV_SMEM>>>(0, c1b, b1g, b1b, b1m, b1v);
    k_conv_mma<<<1024, 256, CONV_SMEM>>>(1, c2b, b2g, b2b, b2m, b2v);
    k_devox  <<<2048, 128, DEVOX_SMEM>>>(coords, mw, mb, bpg, bpb, bpm, bpv, out);
    k_copy   <<<(BB*3*NPTS + 255)/256, 256>>>(coords, out + (size_t)BB*COUT*NPTS);
}